// round 3
// baseline (speedup 1.0000x reference)
#include <cuda_runtime.h>
#include <cstdint>

// ---------------- problem constants ----------------
#define TSEQ   4096
#define EMB    300
#define HID    500
#define HP     512            // padded hidden (zero pad 500..511, never written -> stays 0)
#define GATES  2000           // 4*HID, torch gate order i,f,g,o
#define NCLS   90

// ---------------- persistent-kernel config ----------------
#define NB0    50             // layer-0 CTAs, 10 units each (50*10 = 500 exact)
#define U0     10
#define RPW0   5              // rows per warp, layer 0: 40 rows / 8 warps
#define NB1    84             // layer-1 CTAs, 6 units each (84*6 = 504 >= 500)
#define U1     6
#define RPW1   6              // half-rows per warp, layer 1: 48 / 8 warps
#define NBLK   (NB0 + NB1)    // 134 <= 148 SMs -> all co-resident
#define THREADS 256           // 8 warps

#define F1S    64             // flag row stride (pad NB0=50 -> 64)
#define F2S    96             // flag row stride (pad NB1=84 -> 96)

// ---------------- device scratch (static allocation only) ----------------
__device__ float g_xp0[(size_t)TSEQ * GATES];       // precomputed x-projection, layer 0
__device__ float g_h1[(TSEQ + 1) * HP];             // layer-0 hidden seq (row 0 = zeros, never written)
__device__ float g_h2[(TSEQ + 1) * HP];             // layer-1 hidden seq (row 0 = zeros, never written)
__device__ int   g_f1[(TSEQ + 1) * F1S];            // per-producer flags, layer 0
__device__ int   g_f2[(TSEQ + 1) * F2S];            // per-producer flags, layer 1
__device__ float g_Wt[EMB * GATES];                 // W_ih0 transposed: [e][g]

// ---------------- acquire/release primitives (distinct addresses -> no LTS serialization) ----
__device__ __forceinline__ int ld_acq(const int* p) {
    int v;
    asm volatile("ld.acquire.gpu.global.b32 %0, [%1];" : "=r"(v) : "l"(p) : "memory");
    return v;
}
__device__ __forceinline__ void st_rel(int* p, int v) {
    asm volatile("st.release.gpu.global.b32 [%0], %1;" :: "l"(p), "r"(v) : "memory");
}

// ---------------- init: reset flags every replay (keeps the dependency chain honest) ----
__global__ void k_init() {
    const int n1 = (TSEQ + 1) * F1S;
    const int n2 = (TSEQ + 1) * F2S;
    for (int i = blockIdx.x * blockDim.x + threadIdx.x; i < n1 + n2;
         i += gridDim.x * blockDim.x) {
        if (i < n1) g_f1[i] = (i < F1S) ? 1 : 0;          // row 0 = ready
        else { int j = i - n1; g_f2[j] = (j < F2S) ? 1 : 0; }
    }
}

// ---------------- transpose W_ih0 [2000,300] -> [300,2000] ----------------
__global__ void k_transpose(const float* __restrict__ W) {
    int idx = blockIdx.x * 256 + threadIdx.x;
    if (idx < EMB * GATES) {
        int e = idx / GATES;
        int g = idx % GATES;
        g_Wt[idx] = W[g * EMB + e];
    }
}

// ---------------- x-projection GEMM: xp0[t][g] = emb[seq[t]] . W_ih0[g] + bih0 + bhh0 ----
__global__ void k_xproj(const int* __restrict__ seq,
                        const float* __restrict__ emb,
                        const float* __restrict__ bih0,
                        const float* __restrict__ bhh0) {
    __shared__ __align__(16) float embs[16][304];
    int g  = blockIdx.x * 128 + threadIdx.x;
    int t0 = blockIdx.y * 16;

    for (int idx = threadIdx.x; idx < 16 * 304; idx += 128) {
        int tt = idx / 304, e = idx % 304;
        float v = 0.f;
        if (e < EMB) v = emb[(size_t)seq[t0 + tt] * EMB + e];
        embs[tt][e] = v;
    }
    __syncthreads();

    float acc[16];
    float b = (g < GATES) ? (bih0[g] + bhh0[g]) : 0.f;
#pragma unroll
    for (int tt = 0; tt < 16; tt++) acc[tt] = b;

    for (int e4 = 0; e4 < 75; e4++) {
        float w0 = 0.f, w1 = 0.f, w2 = 0.f, w3 = 0.f;
        if (g < GATES) {
            w0 = g_Wt[(e4 * 4 + 0) * GATES + g];
            w1 = g_Wt[(e4 * 4 + 1) * GATES + g];
            w2 = g_Wt[(e4 * 4 + 2) * GATES + g];
            w3 = g_Wt[(e4 * 4 + 3) * GATES + g];
        }
#pragma unroll
        for (int tt = 0; tt < 16; tt++) {
            float4 ev = *reinterpret_cast<const float4*>(&embs[tt][e4 * 4]);
            acc[tt] = fmaf(ev.x, w0, fmaf(ev.y, w1, fmaf(ev.z, w2, fmaf(ev.w, w3, acc[tt]))));
        }
    }
    if (g < GATES) {
#pragma unroll
        for (int tt = 0; tt < 16; tt++)
            g_xp0[(size_t)(t0 + tt) * GATES + g] = acc[tt];
    }
}

__device__ __forceinline__ float sigf(float x) { return 1.f / (1.f + __expf(-x)); }

// ---------------- persistent 2-layer LSTM recurrence ----------------
// CTAs [0, NB0): layer 0. CTAs [NB0, NBLK): layer 1.
// Sync = per-producer release flags + per-warp acquire-poll + __all_sync.
// NO same-address atomics anywhere on the step path.
__global__ __launch_bounds__(THREADS, 1)
void k_lstm(const float* __restrict__ Whh0,
            const float* __restrict__ Wih1,
            const float* __restrict__ Whh1,
            const float* __restrict__ bih1,
            const float* __restrict__ bhh1) {
    int b   = blockIdx.x;
    int tid = threadIdx.x;
    int w = tid >> 5, l = tid & 31;

    __shared__ float sums[2][48];
    float wreg[6][16];

    if (b < NB0) {
        // ======================= LAYER 0 =======================
        const int ub = b * U0;
#pragma unroll
        for (int j = 0; j < RPW0; j++) {
            int r = w * RPW0 + j;          // 0..39
            int q = r / U0, u = r % U0;
            int grow = q * HID + ub + u;   // ub+u < 500 always (exact tiling)
#pragma unroll
            for (int k = 0; k < 16; k++) {
                int idx = l + 32 * k;
                wreg[j][k] = (idx < HID) ? Whh0[grow * HID + idx] : 0.f;
            }
        }
        float c = 0.f;                     // cell state (gate lanes only)

        for (int t = 0; t < TSEQ; t++) {
            // xp prefetch BEFORE the poll: independent data, DRAM latency hides under wait
            float xp0v = 0.f, xp1v = 0.f, xp2v = 0.f, xp3v = 0.f;
            if (tid < U0) {
                const float* xp = &g_xp0[(size_t)t * GATES + ub + tid];
                xp0v = __ldcg(xp + 0 * HID);
                xp1v = __ldcg(xp + 1 * HID);
                xp2v = __ldcg(xp + 2 * HID);
                xp3v = __ldcg(xp + 3 * HID);
            }

            // all-lane acquire poll on layer-0 flag row t (distinct addrs, plain reads)
            {
                const int* fp = &g_f1[t * F1S + l];
                for (;;) {
                    int v = (l < NB0) ? ld_acq(fp) : 1;
                    if (__all_sync(0xffffffffu, v)) break;
                }
                __syncwarp();
            }

            const float* hr = &g_h1[(size_t)t * HP];
            float x[16];
#pragma unroll
            for (int k = 0; k < 16; k++) x[k] = __ldcg(hr + l + 32 * k);

            float* sb = sums[t & 1];
#pragma unroll
            for (int j = 0; j < RPW0; j++) {
                float acc = 0.f;
#pragma unroll
                for (int k = 0; k < 16; k++) acc = fmaf(wreg[j][k], x[k], acc);
#pragma unroll
                for (int off = 16; off; off >>= 1)
                    acc += __shfl_xor_sync(0xffffffffu, acc, off);
                if (l == 0) sb[w * RPW0 + j] = acc;
            }
            __syncthreads();

            if (w == 0) {
                if (l < U0) {
                    float pi = sb[0 * U0 + l] + xp0v;
                    float pf = sb[1 * U0 + l] + xp1v;
                    float pg = sb[2 * U0 + l] + xp2v;
                    float po = sb[3 * U0 + l] + xp3v;
                    float ig = sigf(pi), fg = sigf(pf), og = sigf(po);
                    float gg = tanhf(pg);
                    c = fg * c + ig * gg;
                    float h = og * tanhf(c);
                    __stcg(&g_h1[(size_t)(t + 1) * HP + ub + l], h);
                }
                __syncwarp();
                if (l == 0) st_rel(&g_f1[(t + 1) * F1S + b], 1);
            }
        }
    } else {
        // ======================= LAYER 1 =======================
        const int bb = b - NB0;
        const int ub = bb * U1;
#pragma unroll
        for (int j = 0; j < RPW1; j++) {
            int hr = w * RPW1 + j;         // 0..47; [0,24)=W_ih1 (x=h1), [24,48)=W_hh1 (x=h2)
            int rl = hr % 24;
            int q = rl / U1, u = rl % U1;
            int ug = ub + u;
            int grow = q * HID + ug;
            const float* W = (hr >= 24) ? Whh1 : Wih1;
#pragma unroll
            for (int k = 0; k < 16; k++) {
                int idx = l + 32 * k;
                wreg[j][k] = (ug < HID && idx < HID) ? W[grow * HID + idx] : 0.f;
            }
        }
        float bg0 = 0.f, bg1 = 0.f, bg2 = 0.f, bg3 = 0.f, c = 0.f;
        if (tid < U1 && (ub + tid) < HID) {
            int base = ub + tid;
            bg0 = bih1[0 * HID + base] + bhh1[0 * HID + base];
            bg1 = bih1[1 * HID + base] + bhh1[1 * HID + base];
            bg2 = bih1[2 * HID + base] + bhh1[2 * HID + base];
            bg3 = bih1[3 * HID + base] + bhh1[3 * HID + base];
        }

        for (int t = 0; t < TSEQ; t++) {
            // combined acquire poll: need h1(t) ready (f1 row t+1, 50 flags)
            // and h2(t-1) ready (f2 row t, 84 flags). <=4 loads/lane, all distinct addrs.
            {
                const int* p1 = &g_f1[(t + 1) * F1S];
                const int* p2 = &g_f2[t * F2S];
                for (;;) {
                    int v = (l < NB0) ? ld_acq(p1 + l) : 1;
                    v &= ld_acq(p2 + l);
                    v &= ld_acq(p2 + l + 32);
                    v &= (l < NB1 - 64) ? ld_acq(p2 + l + 64) : 1;
                    if (__all_sync(0xffffffffu, v)) break;
                }
                __syncwarp();
            }

            const float* xs = (w < 4) ? &g_h1[(size_t)(t + 1) * HP]
                                      : &g_h2[(size_t)t * HP];
            float x[16];
#pragma unroll
            for (int k = 0; k < 16; k++) x[k] = __ldcg(xs + l + 32 * k);

            float* sb = sums[t & 1];
#pragma unroll
            for (int j = 0; j < RPW1; j++) {
                float acc = 0.f;
#pragma unroll
                for (int k = 0; k < 16; k++) acc = fmaf(wreg[j][k], x[k], acc);
#pragma unroll
                for (int off = 16; off; off >>= 1)
                    acc += __shfl_xor_sync(0xffffffffu, acc, off);
                if (l == 0) sb[w * RPW1 + j] = acc;
            }
            __syncthreads();

            if (w == 0) {
                if (l < U1) {
                    float pi = sb[0 * U1 + l] + sb[24 + 0 * U1 + l] + bg0;
                    float pf = sb[1 * U1 + l] + sb[24 + 1 * U1 + l] + bg1;
                    float pg = sb[2 * U1 + l] + sb[24 + 2 * U1 + l] + bg2;
                    float po = sb[3 * U1 + l] + sb[24 + 3 * U1 + l] + bg3;
                    float ig = sigf(pi), fg = sigf(pf), og = sigf(po);
                    float gg = tanhf(pg);
                    c = fg * c + ig * gg;
                    float h = og * tanhf(c);
                    if ((ub + l) < HID)
                        __stcg(&g_h2[(size_t)(t + 1) * HP + ub + l], h);
                }
                __syncwarp();
                if (l == 0) st_rel(&g_f2[(t + 1) * F2S + bb], 1);
            }
        }
    }
}

// ---------------- final FC: out = h2[last] @ fc_W^T + fc_b ----------------
__global__ void k_fc(const float* __restrict__ fcW,
                     const float* __restrict__ fcb,
                     float* __restrict__ out) {
    int b = blockIdx.x;        // class
    int l = threadIdx.x;       // lane
    float acc = 0.f;
    for (int k = l; k < HID; k += 32)
        acc += fcW[b * HID + k] * g_h2[TSEQ * HP + k];
#pragma unroll
    for (int off = 16; off; off >>= 1)
        acc += __shfl_xor_sync(0xffffffffu, acc, off);
    if (l == 0) out[b] = acc + fcb[b];
}

// ---------------- launch ----------------
extern "C" void kernel_launch(void* const* d_in, const int* in_sizes, int n_in,
                              void* d_out, int out_size) {
    const int*   seq  = (const int*)  d_in[0];
    const float* emb  = (const float*)d_in[1];
    const float* Wih0 = (const float*)d_in[2];
    const float* Whh0 = (const float*)d_in[3];
    const float* bih0 = (const float*)d_in[4];
    const float* bhh0 = (const float*)d_in[5];
    const float* Wih1 = (const float*)d_in[6];
    const float* Whh1 = (const float*)d_in[7];
    const float* bih1 = (const float*)d_in[8];
    const float* bhh1 = (const float*)d_in[9];
    const float* fcW  = (const float*)d_in[10];
    const float* fcb  = (const float*)d_in[11];

    k_init<<<148, 256>>>();
    k_transpose<<<(EMB * GATES + 255) / 256, 256>>>(Wih0);
    dim3 gx(16, 256);
    k_xproj<<<gx, 128>>>(seq, emb, bih0, bhh0);
    k_lstm<<<NBLK, THREADS>>>(Whh0, Wih1, Whh1, bih1, bhh1);
    k_fc<<<NCLS, 32>>>(fcW, fcb, (float*)d_out);
}

// round 6
// speedup vs baseline: 1.9332x; 1.9332x over previous
#include <cuda_runtime.h>
#include <cstdint>

// ---------------- problem constants ----------------
#define TSEQ   4096
#define EMB    300
#define HID    500
#define HP     512            // padded hidden (pad 500..511 never written -> stays 0)
#define GATES  2000           // 4*HID, torch gate order i,f,g,o
#define NCLS   90

// ---------------- persistent-kernel config (R2 skeleton, proven resident) ----------------
#define NB0    50             // layer-0 CTAs, 10 units each (50*10 = 500 exact)
#define U0     10
#define RPW0   5              // rows per warp, layer 0: 40 rows / 8 warps
#define NB1    84             // layer-1 CTAs, 6 units each (84*6 = 504 >= 500)
#define U1     6
#define RPW1   6              // half-rows per warp, layer 1: 48 / 8 warps
#define NBLK   (NB0 + NB1)    // 134 <= 148 SMs -> all co-resident at occupancy 1
#define THREADS 256           // 8 warps

#define NGRP   8              // counter groups per layer (one 32B sector per step-row)
// group quotas: 50 = 2*7 + 6*6 ; 84 = 4*11 + 4*10
__device__ __forceinline__ int quota1(int g) { return (g < 2) ? 7 : 6; }
__device__ __forceinline__ int quota2(int g) { return (g < 4) ? 11 : 10; }

// ---------------- device scratch (static allocation only) ----------------
__device__ float g_xp0[(size_t)TSEQ * GATES];       // precomputed x-projection, layer 0
__device__ float g_h1[(TSEQ + 1) * HP];             // layer-0 hidden seq (row 0 = zeros)
__device__ float g_h2[(TSEQ + 1) * HP];             // layer-1 hidden seq (row 0 = zeros)
__device__ int   g_c1[(TSEQ + 1) * NGRP];           // grouped counters, layer 0
__device__ int   g_c2[(TSEQ + 1) * NGRP];           // grouped counters, layer 1
__device__ float g_Wt[EMB * GATES];                 // W_ih0 transposed: [e][g]

// ---------------- acquire/release primitives ----------------
__device__ __forceinline__ int ld_acq(const int* p) {
    int v;
    asm volatile("ld.acquire.gpu.global.b32 %0, [%1];" : "=r"(v) : "l"(p) : "memory");
    return v;
}
__device__ __forceinline__ void red_release(int* p) {
    asm volatile("red.release.gpu.global.add.u32 [%0], 1;" :: "l"(p) : "memory");
}

// ---------------- init: reset counters every replay ----------------
__global__ void k_init() {
    const int n = (TSEQ + 1) * NGRP;
    for (int i = blockIdx.x * blockDim.x + threadIdx.x; i < 2 * n;
         i += gridDim.x * blockDim.x) {
        if (i < n) g_c1[i] = (i < NGRP) ? quota1(i) : 0;        // row 0 = ready
        else { int j = i - n; g_c2[j] = (j < NGRP) ? quota2(j) : 0; }
    }
}

// ---------------- transpose W_ih0 [2000,300] -> [300,2000] ----------------
__global__ void k_transpose(const float* __restrict__ W) {
    int idx = blockIdx.x * 256 + threadIdx.x;
    if (idx < EMB * GATES) {
        int e = idx / GATES;
        int g = idx % GATES;
        g_Wt[idx] = W[g * EMB + e];
    }
}

// ---------------- x-projection GEMM: xp0[t][g] = emb[seq[t]] . W_ih0[g] + bih0 + bhh0 ----
__global__ void k_xproj(const int* __restrict__ seq,
                        const float* __restrict__ emb,
                        const float* __restrict__ bih0,
                        const float* __restrict__ bhh0) {
    __shared__ __align__(16) float embs[16][304];
    int g  = blockIdx.x * 128 + threadIdx.x;
    int t0 = blockIdx.y * 16;

    for (int idx = threadIdx.x; idx < 16 * 304; idx += 128) {
        int tt = idx / 304, e = idx % 304;
        float v = 0.f;
        if (e < EMB) v = emb[(size_t)seq[t0 + tt] * EMB + e];
        embs[tt][e] = v;
    }
    __syncthreads();

    float acc[16];
    float b = (g < GATES) ? (bih0[g] + bhh0[g]) : 0.f;
#pragma unroll
    for (int tt = 0; tt < 16; tt++) acc[tt] = b;

    for (int e4 = 0; e4 < 75; e4++) {
        float w0 = 0.f, w1 = 0.f, w2 = 0.f, w3 = 0.f;
        if (g < GATES) {
            w0 = g_Wt[(e4 * 4 + 0) * GATES + g];
            w1 = g_Wt[(e4 * 4 + 1) * GATES + g];
            w2 = g_Wt[(e4 * 4 + 2) * GATES + g];
            w3 = g_Wt[(e4 * 4 + 3) * GATES + g];
        }
#pragma unroll
        for (int tt = 0; tt < 16; tt++) {
            float4 ev = *reinterpret_cast<const float4*>(&embs[tt][e4 * 4]);
            acc[tt] = fmaf(ev.x, w0, fmaf(ev.y, w1, fmaf(ev.z, w2, fmaf(ev.w, w3, acc[tt]))));
        }
    }
    if (g < GATES) {
#pragma unroll
        for (int tt = 0; tt < 16; tt++)
            g_xp0[(size_t)(t0 + tt) * GATES + g] = acc[tt];
    }
}

__device__ __forceinline__ float sigf(float x)  { return 1.f / (1.f + __expf(-x)); }
__device__ __forceinline__ float tanhfast(float x) { return 1.f - 2.f / (__expf(2.f * x) + 1.f); }

// ---------------- persistent 2-layer LSTM recurrence ----------------
// Grouped-counter sync: producer CTA b release-adds to counter group b&7 (8 distinct
// L2 words per step-row -> <=11 RMWs serialize per word vs 84 before). Consumers poll
// one 32B sector per warp iteration (lanes 0-7 / 8-15), then proceed without a barrier.
__global__ __launch_bounds__(THREADS, 1)
void k_lstm(const float* __restrict__ Whh0,
            const float* __restrict__ Wih1,
            const float* __restrict__ Whh1,
            const float* __restrict__ bih1,
            const float* __restrict__ bhh1) {
    int b   = blockIdx.x;
    int tid = threadIdx.x;
    int w = tid >> 5, l = tid & 31;

    __shared__ float sums[2][48];
    float wreg[6][16];

    if (b < NB0) {
        // ======================= LAYER 0 =======================
        const int ub = b * U0;
        const int grp = b & 7;
#pragma unroll
        for (int j = 0; j < RPW0; j++) {
            int r = w * RPW0 + j;          // 0..39
            int q = r / U0, u = r % U0;
            int grow = q * HID + ub + u;
#pragma unroll
            for (int k = 0; k < 16; k++) {
                int idx = l + 32 * k;
                wreg[j][k] = (idx < HID) ? Whh0[grow * HID + idx] : 0.f;
            }
        }
        float c = 0.f;
        const int need1 = (l < NGRP) ? quota1(l) : 0;

        for (int t = 0; t < TSEQ; t++) {
            // xp prefetch BEFORE the poll (independent data; DRAM latency hides under wait)
            float xp0v = 0.f, xp1v = 0.f, xp2v = 0.f, xp3v = 0.f;
            if (tid < U0) {
                const float* xp = &g_xp0[(size_t)t * GATES + ub + tid];
                xp0v = __ldcg(xp + 0 * HID);
                xp1v = __ldcg(xp + 1 * HID);
                xp2v = __ldcg(xp + 2 * HID);
                xp3v = __ldcg(xp + 3 * HID);
            }

            // all-warp poll: lanes 0-7 each watch one group counter (one 32B sector)
            {
                const int* cp = &g_c1[t * NGRP + (l & 7)];
                for (;;) {
                    int v = (l < NGRP) ? ld_acq(cp) : 0;
                    if (__all_sync(0xffffffffu, v >= need1)) break;
                }
                __syncwarp();
            }

            const float* hr = &g_h1[(size_t)t * HP];
            float x[16];
#pragma unroll
            for (int k = 0; k < 16; k++) x[k] = __ldcg(hr + l + 32 * k);

            float* sb = sums[t & 1];
#pragma unroll
            for (int j = 0; j < RPW0; j++) {
                float acc = 0.f;
#pragma unroll
                for (int k = 0; k < 16; k++) acc = fmaf(wreg[j][k], x[k], acc);
#pragma unroll
                for (int off = 16; off; off >>= 1)
                    acc += __shfl_xor_sync(0xffffffffu, acc, off);
                if (l == 0) sb[w * RPW0 + j] = acc;
            }
            __syncthreads();

            if (w == 0) {
                if (l < U0) {
                    float pi = sb[0 * U0 + l] + xp0v;
                    float pf = sb[1 * U0 + l] + xp1v;
                    float pg = sb[2 * U0 + l] + xp2v;
                    float po = sb[3 * U0 + l] + xp3v;
                    float ig = sigf(pi), fg = sigf(pf), og = sigf(po);
                    float gg = tanhfast(pg);
                    c = fg * c + ig * gg;
                    float h = og * tanhfast(c);
                    __stcg(&g_h1[(size_t)(t + 1) * HP + ub + l], h);
                }
                __syncwarp();
                if (l == 0) red_release(&g_c1[(t + 1) * NGRP + grp]);
            }
        }
    } else {
        // ======================= LAYER 1 =======================
        const int bb = b - NB0;
        const int ub = bb * U1;
        const int grp = bb & 7;
#pragma unroll
        for (int j = 0; j < RPW1; j++) {
            int hr = w * RPW1 + j;         // 0..47; [0,24)=W_ih1 (x=h1), [24,48)=W_hh1 (x=h2)
            int rl = hr % 24;
            int q = rl / U1, u = rl % U1;
            int ug = ub + u;
            int grow = q * HID + ug;
            const float* W = (hr >= 24) ? Whh1 : Wih1;
#pragma unroll
            for (int k = 0; k < 16; k++) {
                int idx = l + 32 * k;
                wreg[j][k] = (ug < HID && idx < HID) ? W[grow * HID + idx] : 0.f;
            }
        }
        float bg0 = 0.f, bg1 = 0.f, bg2 = 0.f, bg3 = 0.f, c = 0.f;
        if (tid < U1 && (ub + tid) < HID) {
            int base = ub + tid;
            bg0 = bih1[0 * HID + base] + bhh1[0 * HID + base];
            bg1 = bih1[1 * HID + base] + bhh1[1 * HID + base];
            bg2 = bih1[2 * HID + base] + bhh1[2 * HID + base];
            bg3 = bih1[3 * HID + base] + bhh1[3 * HID + base];
        }
        // lanes 0-7 watch g_c1 (need quota1), lanes 8-15 watch g_c2 (need quota2)
        const int need = (l < NGRP) ? quota1(l)
                       : (l < 2 * NGRP) ? quota2(l - NGRP) : 0;

        for (int t = 0; t < TSEQ; t++) {
            {
                const int* cp1 = &g_c1[(t + 1) * NGRP + (l & 7)];
                const int* cp2 = &g_c2[t * NGRP + (l & 7)];
                for (;;) {
                    int v = (l < NGRP) ? ld_acq(cp1)
                          : (l < 2 * NGRP) ? ld_acq(cp2) : 0;
                    if (__all_sync(0xffffffffu, v >= need)) break;
                }
                __syncwarp();
            }

            const float* xs = (w < 4) ? &g_h1[(size_t)(t + 1) * HP]
                                      : &g_h2[(size_t)t * HP];
            float x[16];
#pragma unroll
            for (int k = 0; k < 16; k++) x[k] = __ldcg(xs + l + 32 * k);

            float* sb = sums[t & 1];
#pragma unroll
            for (int j = 0; j < RPW1; j++) {
                float acc = 0.f;
#pragma unroll
                for (int k = 0; k < 16; k++) acc = fmaf(wreg[j][k], x[k], acc);
#pragma unroll
                for (int off = 16; off; off >>= 1)
                    acc += __shfl_xor_sync(0xffffffffu, acc, off);
                if (l == 0) sb[w * RPW1 + j] = acc;
            }
            __syncthreads();

            if (w == 0) {
                if (l < U1) {
                    float pi = sb[0 * U1 + l] + sb[24 + 0 * U1 + l] + bg0;
                    float pf = sb[1 * U1 + l] + sb[24 + 1 * U1 + l] + bg1;
                    float pg = sb[2 * U1 + l] + sb[24 + 2 * U1 + l] + bg2;
                    float po = sb[3 * U1 + l] + sb[24 + 3 * U1 + l] + bg3;
                    float ig = sigf(pi), fg = sigf(pf), og = sigf(po);
                    float gg = tanhfast(pg);
                    c = fg * c + ig * gg;
                    float h = og * tanhfast(c);
                    if ((ub + l) < HID)
                        __stcg(&g_h2[(size_t)(t + 1) * HP + ub + l], h);
                }
                __syncwarp();
                if (l == 0) red_release(&g_c2[(t + 1) * NGRP + grp]);
            }
        }
    }
}

// ---------------- final FC: out = h2[last] @ fc_W^T + fc_b ----------------
__global__ void k_fc(const float* __restrict__ fcW,
                     const float* __restrict__ fcb,
                     float* __restrict__ out) {
    int b = blockIdx.x;        // class
    int l = threadIdx.x;       // lane
    float acc = 0.f;
    for (int k = l; k < HID; k += 32)
        acc += fcW[b * HID + k] * g_h2[TSEQ * HP + k];
#pragma unroll
    for (int off = 16; off; off >>= 1)
        acc += __shfl_xor_sync(0xffffffffu, acc, off);
    if (l == 0) out[b] = acc + fcb[b];
}

// ---------------- launch ----------------
extern "C" void kernel_launch(void* const* d_in, const int* in_sizes, int n_in,
                              void* d_out, int out_size) {
    const int*   seq  = (const int*)  d_in[0];
    const float* emb  = (const float*)d_in[1];
    const float* Wih0 = (const float*)d_in[2];
    const float* Whh0 = (const float*)d_in[3];
    const float* bih0 = (const float*)d_in[4];
    const float* bhh0 = (const float*)d_in[5];
    const float* Wih1 = (const float*)d_in[6];
    const float* Whh1 = (const float*)d_in[7];
    const float* bih1 = (const float*)d_in[8];
    const float* bhh1 = (const float*)d_in[9];
    const float* fcW  = (const float*)d_in[10];
    const float* fcb  = (const float*)d_in[11];

    k_init<<<64, 256>>>();
    k_transpose<<<(EMB * GATES + 255) / 256, 256>>>(Wih0);
    dim3 gx(16, 256);
    k_xproj<<<gx, 128>>>(seq, emb, bih0, bhh0);
    k_lstm<<<NBLK, THREADS>>>(Whh0, Wih1, Whh1, bih1, bhh1);
    k_fc<<<NCLS, 32>>>(fcW, fcb, (float*)d_out);
}